// round 1
// baseline (speedup 1.0000x reference)
#include <cuda_runtime.h>

// ADDLoss: out = mean_b( add_b + rot_b + trans_b )
//   add_b  = mean_n || (Rp-Rg) p_n + (tp - tg) ||
//   rot_b  = mean_n || (Rp-Rg) p_n ||
//   trans_b= || tp - tg ||
//
// Inputs (metadata order): pred_r[16384,4] f32, pred_t[16384,3] f32,
//   gt_r[16384,4] f32, gt_t[16384,3] f32, obj_ids[16384] int, points[30,500,3] f32
// Output: 1 float.

#define BATCH      16384
#define NPTS       500
#define NOBJ       30
#define WARPS_PB   8
#define THREADS_PB (WARPS_PB * 32)
#define NBLOCKS    (BATCH / WARPS_PB)   // 2048

__device__ float g_partials[NBLOCKS];

__device__ __forceinline__ float fast_norm(float x2) {
    // ||v|| from ||v||^2 : one MUFU.RSQ + FMUL; guard x2==0 -> 0.
    return x2 * rsqrtf(fmaxf(x2, 1e-30f));
}

__global__ __launch_bounds__(THREADS_PB)
void addloss_stage1(const float* __restrict__ pred_r,
                    const float* __restrict__ pred_t,
                    const float* __restrict__ gt_r,
                    const float* __restrict__ gt_t,
                    const int*   __restrict__ obj_ids,
                    const float* __restrict__ points)
{
    const int warp_in_blk = threadIdx.x >> 5;
    const int lane        = threadIdx.x & 31;
    const int b           = blockIdx.x * WARPS_PB + warp_in_blk;  // batch element

    __shared__ float sh_val[WARPS_PB];

    // ---- per-batch-element setup (redundant across lanes; amortized) ----
    const float4 qp = reinterpret_cast<const float4*>(pred_r)[b];
    const float4 qg = reinterpret_cast<const float4*>(gt_r)[b];

    // Rp
    float pw = qp.x, px_ = qp.y, py_ = qp.z, pz_ = qp.w;
    float p_x2 = px_*px_, p_y2 = py_*py_, p_z2 = pz_*pz_;
    float p_xy = px_*py_, p_xz = px_*pz_, p_yz = py_*pz_;
    float p_wx = pw*px_,  p_wy = pw*py_,  p_wz = pw*pz_;
    // Rg
    float gw = qg.x, gx_ = qg.y, gy_ = qg.z, gz_ = qg.w;
    float g_x2 = gx_*gx_, g_y2 = gy_*gy_, g_z2 = gz_*gz_;
    float g_xy = gx_*gy_, g_xz = gx_*gz_, g_yz = gy_*gz_;
    float g_wx = gw*gx_,  g_wy = gw*gy_,  g_wz = gw*gz_;

    // M = Rp - Rg (the constant 1's cancel on the diagonal)
    const float m00 = -2.f*(p_y2 + p_z2 - g_y2 - g_z2);
    const float m01 =  2.f*(p_xy - p_wz - g_xy + g_wz);
    const float m02 =  2.f*(p_xz + p_wy - g_xz - g_wy);
    const float m10 =  2.f*(p_xy + p_wz - g_xy - g_wz);
    const float m11 = -2.f*(p_x2 + p_z2 - g_x2 - g_z2);
    const float m12 =  2.f*(p_yz - p_wx - g_yz + g_wx);
    const float m20 =  2.f*(p_xz - p_wy - g_xz + g_wy);
    const float m21 =  2.f*(p_yz + p_wx - g_yz - g_wx);
    const float m22 = -2.f*(p_x2 + p_y2 - g_x2 - g_y2);

    const float tx = pred_t[3*b+0] - gt_t[3*b+0];
    const float ty = pred_t[3*b+1] - gt_t[3*b+1];
    const float tz = pred_t[3*b+2] - gt_t[3*b+2];

    int oid = obj_ids[b];
    oid = min(max(oid, 0), NOBJ - 1);
    const float* __restrict__ pbase = points + (size_t)oid * (NPTS * 3);

    // ---- main loop: lane n handles points n, n+32, ... (coalesced) ----
    float s = 0.f;   // accumulates ||Mp|| + ||Mp + t|| over this lane's points
    #pragma unroll 4
    for (int n = lane; n < NPTS; n += 32) {
        const float ptx = pbase[3*n + 0];
        const float pty = pbase[3*n + 1];
        const float ptz = pbase[3*n + 2];
        const float rx = m00*ptx + m01*pty + m02*ptz;
        const float ry = m10*ptx + m11*pty + m12*ptz;
        const float rz = m20*ptx + m21*pty + m22*ptz;
        const float a2 = rx*rx + ry*ry + rz*rz;
        const float dx = rx + tx, dy = ry + ty, dz = rz + tz;
        const float b2 = dx*dx + dy*dy + dz*dz;
        s += fast_norm(a2) + fast_norm(b2);
    }

    // warp reduce (fixed order -> deterministic)
    #pragma unroll
    for (int off = 16; off > 0; off >>= 1)
        s += __shfl_down_sync(0xffffffffu, s, off);

    if (lane == 0) {
        const float trans = fast_norm(tx*tx + ty*ty + tz*tz);
        sh_val[warp_in_blk] = s * (1.0f / NPTS) + trans;
    }
    __syncthreads();

    if (threadIdx.x == 0) {
        float blk = 0.f;
        #pragma unroll
        for (int w = 0; w < WARPS_PB; w++) blk += sh_val[w];
        g_partials[blockIdx.x] = blk;
    }
}

__global__ void addloss_stage2(float* __restrict__ out)
{
    __shared__ float sh[256];
    float s = 0.f;
    for (int i = threadIdx.x; i < NBLOCKS; i += 256)
        s += g_partials[i];
    sh[threadIdx.x] = s;
    __syncthreads();
    #pragma unroll
    for (int st = 128; st > 0; st >>= 1) {
        if (threadIdx.x < st) sh[threadIdx.x] += sh[threadIdx.x + st];
        __syncthreads();
    }
    if (threadIdx.x == 0)
        out[0] = sh[0] * (1.0f / BATCH);
}

extern "C" void kernel_launch(void* const* d_in, const int* in_sizes, int n_in,
                              void* d_out, int out_size)
{
    const float* pred_r  = (const float*)d_in[0];
    const float* pred_t  = (const float*)d_in[1];
    const float* gt_r    = (const float*)d_in[2];
    const float* gt_t    = (const float*)d_in[3];
    const int*   obj_ids = (const int*)  d_in[4];
    const float* points  = (const float*)d_in[5];
    float* out = (float*)d_out;

    addloss_stage1<<<NBLOCKS, THREADS_PB>>>(pred_r, pred_t, gt_r, gt_t, obj_ids, points);
    addloss_stage2<<<1, 256>>>(out);
}

// round 2
// speedup vs baseline: 1.2871x; 1.2871x over previous
#include <cuda_runtime.h>

// ADDLoss fused single-kernel version.
//   out = mean_b( mean_n||Mp_n + t|| + mean_n||Mp_n|| + ||t|| ),  M = Rp-Rg, t = tp-tg
// Per batch element precompute S = M^T M (PSD), c = 2 M^T t, t2 = ||t||^2:
//   ||Mp||^2     = p^T S p
//   ||Mp + t||^2 = p^T S p + c.p + t2
// Final reduction: deterministic fixed-point integer atomics + last-block finish.

#define BATCH      16384
#define NPTS       500
#define NQUADS     (NPTS / 4)           // 125
#define NOBJ       30
#define WARPS_PB   8
#define THREADS_PB (WARPS_PB * 32)
#define NBLOCKS    (BATCH / WARPS_PB)   // 2048

#define FP_SCALE   68719476736.0        // 2^36
#define INV_FP_SCALE (1.0 / 68719476736.0)

__device__ unsigned long long g_sum;    // zero-init at load; self-resets each launch
__device__ unsigned int       g_count;

__device__ __forceinline__ float fast_norm(float x2) {
    // sqrt(x2) via one MUFU.RSQ; clamp tiny-negative rounding and x2==0.
    x2 = fmaxf(x2, 0.0f);
    return x2 * rsqrtf(fmaxf(x2, 1e-30f));
}

__global__ __launch_bounds__(THREADS_PB)
void addloss_fused(const float* __restrict__ pred_r,
                   const float* __restrict__ pred_t,
                   const float* __restrict__ gt_r,
                   const float* __restrict__ gt_t,
                   const int*   __restrict__ obj_ids,
                   const float* __restrict__ points,
                   float*       __restrict__ out)
{
    const int warp_in_blk = threadIdx.x >> 5;
    const int lane        = threadIdx.x & 31;
    const int b           = blockIdx.x * WARPS_PB + warp_in_blk;

    __shared__ float sh_val[WARPS_PB];

    // ---- per-batch-element setup (redundant across lanes; amortized over 500 pts) ----
    const float4 qp = reinterpret_cast<const float4*>(pred_r)[b];
    const float4 qg = reinterpret_cast<const float4*>(gt_r)[b];

    float pw = qp.x, px_ = qp.y, py_ = qp.z, pz_ = qp.w;
    float p_x2 = px_*px_, p_y2 = py_*py_, p_z2 = pz_*pz_;
    float p_xy = px_*py_, p_xz = px_*pz_, p_yz = py_*pz_;
    float p_wx = pw*px_,  p_wy = pw*py_,  p_wz = pw*pz_;
    float gw = qg.x, gx_ = qg.y, gy_ = qg.z, gz_ = qg.w;
    float g_x2 = gx_*gx_, g_y2 = gy_*gy_, g_z2 = gz_*gz_;
    float g_xy = gx_*gy_, g_xz = gx_*gz_, g_yz = gy_*gz_;
    float g_wx = gw*gx_,  g_wy = gw*gy_,  g_wz = gw*gz_;

    // M = Rp - Rg (diagonal 1's cancel)
    const float m00 = -2.f*(p_y2 + p_z2 - g_y2 - g_z2);
    const float m01 =  2.f*(p_xy - p_wz - g_xy + g_wz);
    const float m02 =  2.f*(p_xz + p_wy - g_xz - g_wy);
    const float m10 =  2.f*(p_xy + p_wz - g_xy - g_wz);
    const float m11 = -2.f*(p_x2 + p_z2 - g_x2 - g_z2);
    const float m12 =  2.f*(p_yz - p_wx - g_yz + g_wx);
    const float m20 =  2.f*(p_xz - p_wy - g_xz + g_wy);
    const float m21 =  2.f*(p_yz + p_wx - g_yz - g_wx);
    const float m22 = -2.f*(p_x2 + p_y2 - g_x2 - g_y2);

    const float tx = pred_t[3*b+0] - gt_t[3*b+0];
    const float ty = pred_t[3*b+1] - gt_t[3*b+1];
    const float tz = pred_t[3*b+2] - gt_t[3*b+2];
    const float t2 = tx*tx + ty*ty + tz*tz;

    // S = M^T M (off-diagonals pre-doubled), c = 2 M^T t
    const float s00  = m00*m00 + m10*m10 + m20*m20;
    const float s11  = m01*m01 + m11*m11 + m21*m21;
    const float s22  = m02*m02 + m12*m12 + m22*m22;
    const float s01d = 2.f*(m00*m01 + m10*m11 + m20*m21);
    const float s02d = 2.f*(m00*m02 + m10*m12 + m20*m22);
    const float s12d = 2.f*(m01*m02 + m11*m12 + m21*m22);
    const float c0   = 2.f*(m00*tx + m10*ty + m20*tz);
    const float c1   = 2.f*(m01*tx + m11*ty + m21*tz);
    const float c2   = 2.f*(m02*tx + m12*ty + m22*tz);

    int oid = obj_ids[b];
    oid = min(max(oid, 0), NOBJ - 1);
    // object offset = oid*1500 floats = 6000 bytes -> 16B aligned, float4 legal
    const float4* __restrict__ pb4 =
        reinterpret_cast<const float4*>(points + (size_t)oid * (NPTS * 3));

    float s = 0.f;

    // lane handles point-quads: 3x LDG.128 per 4 points
    #define POINT_TERM(PX, PY, PZ) do {                                        \
        const float _px = (PX), _py = (PY), _pz = (PZ);                        \
        const float _xx = _px*_px, _yy = _py*_py, _zz = _pz*_pz;               \
        const float _xy = _px*_py, _xz = _px*_pz, _yz = _py*_pz;               \
        float _a2 = s00*_xx + s11*_yy + s22*_zz                                \
                  + s01d*_xy + s02d*_xz + s12d*_yz;                            \
        float _lin = fmaf(c0, _px, fmaf(c1, _py, fmaf(c2, _pz, t2)));          \
        float _b2 = _a2 + _lin;                                                \
        s += fast_norm(_a2) + fast_norm(_b2);                                  \
    } while (0)

    for (int q = lane; q < NQUADS; q += 32) {
        const float4 v0 = pb4[3*q + 0];
        const float4 v1 = pb4[3*q + 1];
        const float4 v2 = pb4[3*q + 2];
        POINT_TERM(v0.x, v0.y, v0.z);
        POINT_TERM(v0.w, v1.x, v1.y);
        POINT_TERM(v1.z, v1.w, v2.x);
        POINT_TERM(v2.y, v2.z, v2.w);
    }
    #undef POINT_TERM

    // warp reduce (fixed order -> deterministic)
    #pragma unroll
    for (int off = 16; off > 0; off >>= 1)
        s += __shfl_down_sync(0xffffffffu, s, off);

    if (lane == 0)
        sh_val[warp_in_blk] = s * (1.0f / NPTS) + fast_norm(t2);
    __syncthreads();

    if (threadIdx.x == 0) {
        float blk = 0.f;
        #pragma unroll
        for (int w = 0; w < WARPS_PB; w++) blk += sh_val[w];

        // deterministic grid reduction: fixed-point integer atomic (exact commutativity)
        const unsigned long long q =
            (unsigned long long)__double2ll_rn((double)blk * FP_SCALE);
        atomicAdd(&g_sum, q);
        __threadfence();
        const unsigned int ticket = atomicAdd(&g_count, 1u);
        if (ticket == NBLOCKS - 1) {
            const unsigned long long total = atomicExch(&g_sum, 0ULL); // read + reset
            g_count = 0u;                                              // reset for replay
            out[0] = (float)((double)total * INV_FP_SCALE * (1.0 / BATCH));
        }
    }
}

extern "C" void kernel_launch(void* const* d_in, const int* in_sizes, int n_in,
                              void* d_out, int out_size)
{
    const float* pred_r  = (const float*)d_in[0];
    const float* pred_t  = (const float*)d_in[1];
    const float* gt_r    = (const float*)d_in[2];
    const float* gt_t    = (const float*)d_in[3];
    const int*   obj_ids = (const int*)  d_in[4];
    const float* points  = (const float*)d_in[5];
    float* out = (float*)d_out;

    addloss_fused<<<NBLOCKS, THREADS_PB>>>(pred_r, pred_t, gt_r, gt_t,
                                           obj_ids, points, out);
}

// round 3
// speedup vs baseline: 1.3046x; 1.0135x over previous
#include <cuda_runtime.h>

// ADDLoss fused single-kernel, packed f32x2 math (sm_103a FFMA2 path).
//   out = mean_b( mean_n||Mp_n + t|| + mean_n||Mp_n|| + ||t|| ),  M = Rp-Rg, t = tp-tg
// Per batch element: S = M^T M (off-diag doubled), c = 2 M^T t, t2 = ||t||^2.
//   ||Mp||^2     = p^T S p           (Horner, packed 2 points/op)
//   ||Mp + t||^2 = p^T S p + c.p + t2
// Norm via sqrt.approx.f32 (1 MUFU). Grid reduce: fixed-point int atomics (deterministic).

#define BATCH      16384
#define NPTS       500
#define NQUADS     (NPTS / 4)           // 125
#define NOBJ       30
#define WARPS_PB   8
#define THREADS_PB (WARPS_PB * 32)
#define NBLOCKS    (BATCH / WARPS_PB)   // 2048

#define FP_SCALE     68719476736.0      // 2^36
#define INV_FP_SCALE (1.0 / 68719476736.0)

__device__ unsigned long long g_sum;
__device__ unsigned int       g_count;

typedef unsigned long long u64;

__device__ __forceinline__ u64 pack2(float lo, float hi) {
    u64 d; asm("mov.b64 %0, {%1, %2};" : "=l"(d) : "f"(lo), "f"(hi)); return d;
}
__device__ __forceinline__ void unpack2(float& lo, float& hi, u64 v) {
    asm("mov.b64 {%0, %1}, %2;" : "=f"(lo), "=f"(hi) : "l"(v));
}
__device__ __forceinline__ u64 mul2(u64 a, u64 b) {
    u64 d; asm("mul.rn.f32x2 %0, %1, %2;" : "=l"(d) : "l"(a), "l"(b)); return d;
}
__device__ __forceinline__ u64 add2(u64 a, u64 b) {
    u64 d; asm("add.rn.f32x2 %0, %1, %2;" : "=l"(d) : "l"(a), "l"(b)); return d;
}
__device__ __forceinline__ u64 fma2(u64 a, u64 b, u64 c) {
    u64 d; asm("fma.rn.f32x2 %0, %1, %2, %3;" : "=l"(d) : "l"(a), "l"(b), "l"(c)); return d;
}
__device__ __forceinline__ float sqrt_approx(float x) {
    float r; asm("sqrt.approx.f32 %0, %1;" : "=f"(r) : "f"(fmaxf(x, 0.0f))); return r;
}

__global__ __launch_bounds__(THREADS_PB)
void addloss_fused(const float* __restrict__ pred_r,
                   const float* __restrict__ pred_t,
                   const float* __restrict__ gt_r,
                   const float* __restrict__ gt_t,
                   const int*   __restrict__ obj_ids,
                   const float* __restrict__ points,
                   float*       __restrict__ out)
{
    const int warp_in_blk = threadIdx.x >> 5;
    const int lane        = threadIdx.x & 31;
    const int b           = blockIdx.x * WARPS_PB + warp_in_blk;

    __shared__ float sh_val[WARPS_PB];

    // ---- per-batch-element setup (redundant across lanes; amortized over 500 pts) ----
    const float4 qp = reinterpret_cast<const float4*>(pred_r)[b];
    const float4 qg = reinterpret_cast<const float4*>(gt_r)[b];

    float pw = qp.x, px_ = qp.y, py_ = qp.z, pz_ = qp.w;
    float p_x2 = px_*px_, p_y2 = py_*py_, p_z2 = pz_*pz_;
    float p_xy = px_*py_, p_xz = px_*pz_, p_yz = py_*pz_;
    float p_wx = pw*px_,  p_wy = pw*py_,  p_wz = pw*pz_;
    float gw = qg.x, gx_ = qg.y, gy_ = qg.z, gz_ = qg.w;
    float g_x2 = gx_*gx_, g_y2 = gy_*gy_, g_z2 = gz_*gz_;
    float g_xy = gx_*gy_, g_xz = gx_*gz_, g_yz = gy_*gz_;
    float g_wx = gw*gx_,  g_wy = gw*gy_,  g_wz = gw*gz_;

    const float m00 = -2.f*(p_y2 + p_z2 - g_y2 - g_z2);
    const float m01 =  2.f*(p_xy - p_wz - g_xy + g_wz);
    const float m02 =  2.f*(p_xz + p_wy - g_xz - g_wy);
    const float m10 =  2.f*(p_xy + p_wz - g_xy - g_wz);
    const float m11 = -2.f*(p_x2 + p_z2 - g_x2 - g_z2);
    const float m12 =  2.f*(p_yz - p_wx - g_yz + g_wx);
    const float m20 =  2.f*(p_xz - p_wy - g_xz + g_wy);
    const float m21 =  2.f*(p_yz + p_wx - g_yz - g_wx);
    const float m22 = -2.f*(p_x2 + p_y2 - g_x2 - g_y2);

    const float tx = pred_t[3*b+0] - gt_t[3*b+0];
    const float ty = pred_t[3*b+1] - gt_t[3*b+1];
    const float tz = pred_t[3*b+2] - gt_t[3*b+2];
    const float t2s = tx*tx + ty*ty + tz*tz;

    // Packed (broadcast) coefficients: S = M^T M (off-diag doubled), c = 2 M^T t
    const u64 S00 = pack2(m00*m00 + m10*m10 + m20*m20, m00*m00 + m10*m10 + m20*m20);
    const u64 S11 = pack2(m01*m01 + m11*m11 + m21*m21, m01*m01 + m11*m11 + m21*m21);
    const u64 S22 = pack2(m02*m02 + m12*m12 + m22*m22, m02*m02 + m12*m12 + m22*m22);
    const float s01 = 2.f*(m00*m01 + m10*m11 + m20*m21);
    const float s02 = 2.f*(m00*m02 + m10*m12 + m20*m22);
    const float s12 = 2.f*(m01*m02 + m11*m12 + m21*m22);
    const u64 S01 = pack2(s01, s01);
    const u64 S02 = pack2(s02, s02);
    const u64 S12 = pack2(s12, s12);
    const float c0s = 2.f*(m00*tx + m10*ty + m20*tz);
    const float c1s = 2.f*(m01*tx + m11*ty + m21*tz);
    const float c2s = 2.f*(m02*tx + m12*ty + m22*tz);
    const u64 C0 = pack2(c0s, c0s);
    const u64 C1 = pack2(c1s, c1s);
    const u64 C2 = pack2(c2s, c2s);
    const u64 T2 = pack2(t2s, t2s);

    int oid = obj_ids[b];
    oid = min(max(oid, 0), NOBJ - 1);
    const float4* __restrict__ pb4 =
        reinterpret_cast<const float4*>(points + (size_t)oid * (NPTS * 3));

    float acc0 = 0.f, acc1 = 0.f;   // two accumulators for ILP

    // One packed pair = 2 points: 13 f32x2 ops + 4 norms.
    #define PAIR_TERM(AX,AY,AZ, BX,BY,BZ, ACC_A, ACC_B) do {                   \
        const u64 PX = pack2((AX),(BX));                                       \
        const u64 PY = pack2((AY),(BY));                                       \
        const u64 PZ = pack2((AZ),(BZ));                                       \
        u64 U = fma2(S02, PZ, fma2(S01, PY, mul2(S00, PX)));                   \
        u64 V = fma2(S12, PZ, mul2(S11, PY));                                  \
        u64 W = mul2(S22, PZ);                                                 \
        u64 A2 = fma2(PZ, W, fma2(PY, V, mul2(PX, U)));                        \
        u64 LIN = fma2(C0, PX, fma2(C1, PY, fma2(C2, PZ, T2)));                \
        u64 B2 = add2(A2, LIN);                                                \
        float a2l, a2h, b2l, b2h;                                              \
        unpack2(a2l, a2h, A2);                                                 \
        unpack2(b2l, b2h, B2);                                                 \
        ACC_A += sqrt_approx(a2l) + sqrt_approx(b2l);                          \
        ACC_B += sqrt_approx(a2h) + sqrt_approx(b2h);                          \
    } while (0)

    for (int q = lane; q < NQUADS; q += 32) {
        const float4 v0 = pb4[3*q + 0];
        const float4 v1 = pb4[3*q + 1];
        const float4 v2 = pb4[3*q + 2];
        PAIR_TERM(v0.x, v0.y, v0.z,  v0.w, v1.x, v1.y, acc0, acc1);
        PAIR_TERM(v1.z, v1.w, v2.x,  v2.y, v2.z, v2.w, acc0, acc1);
    }
    #undef PAIR_TERM

    float s = acc0 + acc1;

    // warp reduce (fixed order -> deterministic)
    #pragma unroll
    for (int off = 16; off > 0; off >>= 1)
        s += __shfl_down_sync(0xffffffffu, s, off);

    if (lane == 0)
        sh_val[warp_in_blk] = s * (1.0f / NPTS) + sqrt_approx(t2s);
    __syncthreads();

    if (threadIdx.x == 0) {
        float blk = 0.f;
        #pragma unroll
        for (int w = 0; w < WARPS_PB; w++) blk += sh_val[w];

        // deterministic grid reduction: fixed-point integer atomic (exact commutativity)
        const u64 q = (u64)__double2ll_rn((double)blk * FP_SCALE);
        atomicAdd(&g_sum, q);
        __threadfence();
        const unsigned int ticket = atomicAdd(&g_count, 1u);
        if (ticket == NBLOCKS - 1) {
            const u64 total = atomicExch(&g_sum, 0ULL);  // read + reset for replay
            g_count = 0u;
            out[0] = (float)((double)total * INV_FP_SCALE * (1.0 / BATCH));
        }
    }
}

extern "C" void kernel_launch(void* const* d_in, const int* in_sizes, int n_in,
                              void* d_out, int out_size)
{
    const float* pred_r  = (const float*)d_in[0];
    const float* pred_t  = (const float*)d_in[1];
    const float* gt_r    = (const float*)d_in[2];
    const float* gt_t    = (const float*)d_in[3];
    const int*   obj_ids = (const int*)  d_in[4];
    const float* points  = (const float*)d_in[5];
    float* out = (float*)d_out;

    addloss_fused<<<NBLOCKS, THREADS_PB>>>(pred_r, pred_t, gt_r, gt_t,
                                           obj_ids, points, out);
}

// round 4
// speedup vs baseline: 1.3339x; 1.0225x over previous
#include <cuda_runtime.h>

// ADDLoss, f32x2-packed with SoA-pair point layout.
//   out = mean_b( mean_n||Mp_n + t|| + mean_n||Mp_n|| + ||t|| ),  M = Rp-Rg, t = tp-tg
// Per batch elem: S = M^T M (off-diag doubled), c = 2 M^T t, t2 = ||t||^2:
//   ||Mp||^2 = p^T S p ,  ||Mp+t||^2 = p^T S p + c.p + t2
// Prep kernel packs points into (PX,PY,PZ) u64 pair arrays so the hot loop's
// f32x2 ops need no pack/unpack MOVs (R3 lesson: packing from float4 lanes
// doubled ALU work). Grid reduce: deterministic fixed-point int atomics.

#define BATCH      16384
#define NPTS       500
#define NPAIRS     250
#define NQUADS     125                  // 4 points / quad
#define NOBJ       30
#define OBJ_STRIDE 256                  // u64 pairs per object (padded from 250)
#define WARPS_PB   8
#define THREADS_PB (WARPS_PB * 32)
#define NBLOCKS    (BATCH / WARPS_PB)   // 2048

#define FP_SCALE     68719476736.0      // 2^36
#define INV_FP_SCALE (1.0 / 68719476736.0)

typedef unsigned long long u64;

__device__ u64 g_px[NOBJ * OBJ_STRIDE];
__device__ u64 g_py[NOBJ * OBJ_STRIDE];
__device__ u64 g_pz[NOBJ * OBJ_STRIDE];
__device__ u64 g_sum;
__device__ unsigned int g_count;

__device__ __forceinline__ u64 pack2(float lo, float hi) {
    u64 d; asm("mov.b64 %0, {%1, %2};" : "=l"(d) : "f"(lo), "f"(hi)); return d;
}
__device__ __forceinline__ void unpack2(float& lo, float& hi, u64 v) {
    asm("mov.b64 {%0, %1}, %2;" : "=f"(lo), "=f"(hi) : "l"(v));
}
__device__ __forceinline__ u64 mul2(u64 a, u64 b) {
    u64 d; asm("mul.rn.f32x2 %0, %1, %2;" : "=l"(d) : "l"(a), "l"(b)); return d;
}
__device__ __forceinline__ u64 add2(u64 a, u64 b) {
    u64 d; asm("add.rn.f32x2 %0, %1, %2;" : "=l"(d) : "l"(a), "l"(b)); return d;
}
__device__ __forceinline__ u64 fma2(u64 a, u64 b, u64 c) {
    u64 d; asm("fma.rn.f32x2 %0, %1, %2, %3;" : "=l"(d) : "l"(a), "l"(b), "l"(c)); return d;
}
__device__ __forceinline__ float sqrt_approx(float x) {
    float r; asm("sqrt.approx.f32 %0, %1;" : "=f"(r) : "f"(fmaxf(x, 0.0f))); return r;
}

// ---- prep: AoS points -> SoA u64 pairs -------------------------------------
__global__ void addloss_prep(const float* __restrict__ points)
{
    const int o = blockIdx.x;
    const int j = threadIdx.x;           // pair index
    if (j >= NPAIRS) return;
    const float* p = points + (size_t)o * (NPTS * 3) + 6 * j;
    g_px[o * OBJ_STRIDE + j] = pack2(p[0], p[3]);
    g_py[o * OBJ_STRIDE + j] = pack2(p[1], p[4]);
    g_pz[o * OBJ_STRIDE + j] = pack2(p[2], p[5]);
}

// ---- main ------------------------------------------------------------------
__global__ __launch_bounds__(THREADS_PB)
void addloss_fused(const float* __restrict__ pred_r,
                   const float* __restrict__ pred_t,
                   const float* __restrict__ gt_r,
                   const float* __restrict__ gt_t,
                   const int*   __restrict__ obj_ids,
                   float*       __restrict__ out)
{
    const int warp_in_blk = threadIdx.x >> 5;
    const int lane        = threadIdx.x & 31;
    const int b           = blockIdx.x * WARPS_PB + warp_in_blk;

    __shared__ float sh_val[WARPS_PB];

    // ---- per-batch-element setup (redundant across lanes; amortized) ----
    const float4 qp = reinterpret_cast<const float4*>(pred_r)[b];
    const float4 qg = reinterpret_cast<const float4*>(gt_r)[b];

    float pw = qp.x, px_ = qp.y, py_ = qp.z, pz_ = qp.w;
    float p_x2 = px_*px_, p_y2 = py_*py_, p_z2 = pz_*pz_;
    float p_xy = px_*py_, p_xz = px_*pz_, p_yz = py_*pz_;
    float p_wx = pw*px_,  p_wy = pw*py_,  p_wz = pw*pz_;
    float gw = qg.x, gx_ = qg.y, gy_ = qg.z, gz_ = qg.w;
    float g_x2 = gx_*gx_, g_y2 = gy_*gy_, g_z2 = gz_*gz_;
    float g_xy = gx_*gy_, g_xz = gx_*gz_, g_yz = gy_*gz_;
    float g_wx = gw*gx_,  g_wy = gw*gy_,  g_wz = gw*gz_;

    const float m00 = -2.f*(p_y2 + p_z2 - g_y2 - g_z2);
    const float m01 =  2.f*(p_xy - p_wz - g_xy + g_wz);
    const float m02 =  2.f*(p_xz + p_wy - g_xz - g_wy);
    const float m10 =  2.f*(p_xy + p_wz - g_xy - g_wz);
    const float m11 = -2.f*(p_x2 + p_z2 - g_x2 - g_z2);
    const float m12 =  2.f*(p_yz - p_wx - g_yz + g_wx);
    const float m20 =  2.f*(p_xz - p_wy - g_xz + g_wy);
    const float m21 =  2.f*(p_yz + p_wx - g_yz - g_wx);
    const float m22 = -2.f*(p_x2 + p_y2 - g_x2 - g_y2);

    const float tx = pred_t[3*b+0] - gt_t[3*b+0];
    const float ty = pred_t[3*b+1] - gt_t[3*b+1];
    const float tz = pred_t[3*b+2] - gt_t[3*b+2];
    const float t2s = tx*tx + ty*ty + tz*tz;

    const float s00 = m00*m00 + m10*m10 + m20*m20;
    const float s11 = m01*m01 + m11*m11 + m21*m21;
    const float s22 = m02*m02 + m12*m12 + m22*m22;
    const float s01 = 2.f*(m00*m01 + m10*m11 + m20*m21);
    const float s02 = 2.f*(m00*m02 + m10*m12 + m20*m22);
    const float s12 = 2.f*(m01*m02 + m11*m12 + m21*m22);
    const float c0s = 2.f*(m00*tx + m10*ty + m20*tz);
    const float c1s = 2.f*(m01*tx + m11*ty + m21*tz);
    const float c2s = 2.f*(m02*tx + m12*ty + m22*tz);

    const u64 S00 = pack2(s00, s00), S11 = pack2(s11, s11), S22 = pack2(s22, s22);
    const u64 S01 = pack2(s01, s01), S02 = pack2(s02, s02), S12 = pack2(s12, s12);
    const u64 C0  = pack2(c0s, c0s), C1  = pack2(c1s, c1s), C2  = pack2(c2s, c2s);
    const u64 T2  = pack2(t2s, t2s);

    int oid = obj_ids[b];
    oid = min(max(oid, 0), NOBJ - 1);
    const ulonglong2* __restrict__ BX =
        reinterpret_cast<const ulonglong2*>(g_px) + oid * (OBJ_STRIDE / 2);
    const ulonglong2* __restrict__ BY =
        reinterpret_cast<const ulonglong2*>(g_py) + oid * (OBJ_STRIDE / 2);
    const ulonglong2* __restrict__ BZ =
        reinterpret_cast<const ulonglong2*>(g_pz) + oid * (OBJ_STRIDE / 2);

    float acc0 = 0.f, acc1 = 0.f;

    // One pair (2 points): 13 packed ops + 4 (fmax+MUFU) + 4 FADD, zero MOVs.
    #define PAIR_TERM(PX, PY, PZ) do {                                         \
        u64 U  = fma2(S02, (PZ), fma2(S01, (PY), mul2(S00, (PX))));            \
        u64 V  = fma2(S12, (PZ), mul2(S11, (PY)));                             \
        u64 W  = mul2(S22, (PZ));                                              \
        u64 A2 = fma2((PZ), W, fma2((PY), V, mul2((PX), U)));                  \
        u64 LIN = fma2(C0, (PX), fma2(C1, (PY), fma2(C2, (PZ), T2)));          \
        u64 B2 = add2(A2, LIN);                                                \
        float a2l, a2h, b2l, b2h;                                              \
        unpack2(a2l, a2h, A2);                                                 \
        unpack2(b2l, b2h, B2);                                                 \
        acc0 += sqrt_approx(a2l) + sqrt_approx(b2l);                           \
        acc1 += sqrt_approx(a2h) + sqrt_approx(b2h);                           \
    } while (0)

    #define QUAD(Q) do {                                                       \
        const ulonglong2 vx = BX[(Q)];                                         \
        const ulonglong2 vy = BY[(Q)];                                         \
        const ulonglong2 vz = BZ[(Q)];                                         \
        PAIR_TERM(vx.x, vy.x, vz.x);                                           \
        PAIR_TERM(vx.y, vy.y, vz.y);                                           \
    } while (0)

    // 125 quads, lane-strided, fully unrolled: 3 unconditional + 1 predicated.
    QUAD(lane);
    QUAD(lane + 32);
    QUAD(lane + 64);
    if (lane < NQUADS - 96)   // lane < 29
        QUAD(lane + 96);

    #undef QUAD
    #undef PAIR_TERM

    float s = acc0 + acc1;

    #pragma unroll
    for (int off = 16; off > 0; off >>= 1)
        s += __shfl_down_sync(0xffffffffu, s, off);

    if (lane == 0)
        sh_val[warp_in_blk] = s * (1.0f / NPTS) + sqrt_approx(t2s);
    __syncthreads();

    if (threadIdx.x == 0) {
        float blk = 0.f;
        #pragma unroll
        for (int w = 0; w < WARPS_PB; w++) blk += sh_val[w];

        const u64 q = (u64)__double2ll_rn((double)blk * FP_SCALE);
        atomicAdd(&g_sum, q);
        __threadfence();
        const unsigned int ticket = atomicAdd(&g_count, 1u);
        if (ticket == NBLOCKS - 1) {
            const u64 total = atomicExch(&g_sum, 0ULL);  // read + reset for replay
            g_count = 0u;
            out[0] = (float)((double)total * INV_FP_SCALE * (1.0 / BATCH));
        }
    }
}

extern "C" void kernel_launch(void* const* d_in, const int* in_sizes, int n_in,
                              void* d_out, int out_size)
{
    const float* pred_r  = (const float*)d_in[0];
    const float* pred_t  = (const float*)d_in[1];
    const float* gt_r    = (const float*)d_in[2];
    const float* gt_t    = (const float*)d_in[3];
    const int*   obj_ids = (const int*)  d_in[4];
    const float* points  = (const float*)d_in[5];
    float* out = (float*)d_out;

    addloss_prep<<<NOBJ, 256>>>(points);
    addloss_fused<<<NBLOCKS, THREADS_PB>>>(pred_r, pred_t, gt_r, gt_t,
                                           obj_ids, out);
}